// round 2
// baseline (speedup 1.0000x reference)
#include <cuda_runtime.h>
#include <cuda_bf16.h>
#include <mma.h>

using namespace nvcuda;

#define N_NODES_MAX 100000
#define D_K 256     // D_IN
#define D_N 256     // D_OUT

// Scratch: per-node degree counters (allocation-free rule -> __device__ global)
__device__ int g_deg[N_NODES_MAX];

// ---------------------------------------------------------------------------
// Kernel 1: zero the degree counters (graph replays require re-zeroing)
// ---------------------------------------------------------------------------
__global__ void zero_deg_kernel(int n) {
    int i = blockIdx.x * blockDim.x + threadIdx.x;
    if (i < n) g_deg[i] = 0;
}

// ---------------------------------------------------------------------------
// Kernel 2: degree histogram over edge sources (edge_index[0, :])
// ---------------------------------------------------------------------------
__global__ void hist_kernel(const int* __restrict__ src, int n_edges) {
    int i = blockIdx.x * blockDim.x + threadIdx.x;
    int stride = gridDim.x * blockDim.x;
    int n4 = n_edges >> 2;
    const int4* src4 = reinterpret_cast<const int4*>(src);
    for (int j = i; j < n4; j += stride) {
        int4 v = __ldg(&src4[j]);
        atomicAdd(&g_deg[v.x], 1);
        atomicAdd(&g_deg[v.y], 1);
        atomicAdd(&g_deg[v.z], 1);
        atomicAdd(&g_deg[v.w], 1);
    }
    for (int j = (n4 << 2) + i; j < n_edges; j += stride) {
        atomicAdd(&g_deg[__ldg(&src[j])], 1);
    }
}

// ---------------------------------------------------------------------------
// Kernel 3: out = diag(1 + deg) * (x @ W^T) + b
// tf32 tensor-core GEMM; deg pre-scaled + tf32-rounded at A-tile load.
//
// Block tile: 128 (rows) x 128 (cols), BK = 32.
// grid = (2, numRowTiles): column block varies FASTEST so the two CTAs
// covering the same 128 rows are adjacent in schedule -> x hits L2 on the
// second read instead of streaming from DRAM twice.
//
// 8 warps: wrow = wid % 4 (32-row slice), wcol = wid / 4 (64-col slice),
// 2x4 accumulator fragments of 16x16, k-step 8.
// ---------------------------------------------------------------------------
#define BM 128
#define BN 128
#define BK 32
#define ASTRIDE 40   // 160 B row stride: pads away smem bank conflicts
#define BSTRIDE 40

__global__ __launch_bounds__(256, 2)
void gemm_scaled_kernel(const float* __restrict__ x,
                        const float* __restrict__ W,
                        const float* __restrict__ bias,
                        float* __restrict__ out,
                        int M) {
    __shared__ __align__(32) float As[BM * ASTRIDE];   // 20480 B
    __shared__ __align__(32) float Bs[BN * BSTRIDE];   // 20480 B

    const int tid  = threadIdx.x;
    const int wid  = tid >> 5;
    const int lane = tid & 31;
    const int wrow = wid & 3;   // 0..3 -> 32-row slice
    const int wcol = wid >> 2;  // 0..1 -> 64-col slice

    const int row0 = blockIdx.y * BM;   // global row base of block
    const int col0 = blockIdx.x * BN;   // global col base (0 or 128)

    // Each thread loads 4 fixed A-rows across the k-loop: hoist deg scale.
    const int ar = tid >> 3;            // base row 0..31
    const int ac4 = tid & 7;            // float4 column 0..7
    float dscale[4];
#pragma unroll
    for (int it = 0; it < 4; it++) {
        int gr = row0 + ar + it * 32;
        dscale[it] = (gr < M) ? (1.0f + (float)g_deg[gr]) : 0.0f;
    }

    wmma::fragment<wmma::accumulator, 16, 16, 8, float> acc[2][4];
#pragma unroll
    for (int i = 0; i < 2; i++)
#pragma unroll
        for (int j = 0; j < 4; j++)
            wmma::fill_fragment(acc[i][j], 0.0f);

    for (int k0 = 0; k0 < D_K; k0 += BK) {
        // ---- A tile (deg-prescaled, tf32-rounded): BM x BK ----
#pragma unroll
        for (int it = 0; it < 4; it++) {
            int r  = ar + it * 32;
            int gr = row0 + r;
            float4 v = make_float4(0.f, 0.f, 0.f, 0.f);
            if (gr < M)
                v = __ldg(reinterpret_cast<const float4*>(&x[(size_t)gr * D_K + k0 + ac4 * 4]));
            float d = dscale[it];
            float* dst = &As[r * ASTRIDE + ac4 * 4];
            dst[0] = wmma::__float_to_tf32(d * v.x);
            dst[1] = wmma::__float_to_tf32(d * v.y);
            dst[2] = wmma::__float_to_tf32(d * v.z);
            dst[3] = wmma::__float_to_tf32(d * v.w);
        }
        // ---- B tile: Bs[n][k] = W[col0+n][k0+k] (col-major for wmma) ----
#pragma unroll
        for (int it = 0; it < 4; it++) {
            int idx = tid + it * 256;
            int n  = idx >> 3;
            int c4 = idx & 7;
            float4 v = __ldg(reinterpret_cast<const float4*>(&W[(size_t)(col0 + n) * D_K + k0 + c4 * 4]));
            float* dst = &Bs[n * BSTRIDE + c4 * 4];
            dst[0] = wmma::__float_to_tf32(v.x);
            dst[1] = wmma::__float_to_tf32(v.y);
            dst[2] = wmma::__float_to_tf32(v.z);
            dst[3] = wmma::__float_to_tf32(v.w);
        }
        __syncthreads();

        // ---- MMA over this K chunk (data already tf32-rounded) ----
#pragma unroll
        for (int kk = 0; kk < BK; kk += 8) {
            wmma::fragment<wmma::matrix_a, 16, 16, 8, wmma::precision::tf32, wmma::row_major> af[2];
            wmma::fragment<wmma::matrix_b, 16, 16, 8, wmma::precision::tf32, wmma::col_major> bf[4];
#pragma unroll
            for (int i = 0; i < 2; i++)
                wmma::load_matrix_sync(af[i], &As[(wrow * 32 + i * 16) * ASTRIDE + kk], ASTRIDE);
#pragma unroll
            for (int j = 0; j < 4; j++)
                wmma::load_matrix_sync(bf[j], &Bs[(wcol * 64 + j * 16) * BSTRIDE + kk], BSTRIDE);
#pragma unroll
            for (int i = 0; i < 2; i++)
#pragma unroll
                for (int j = 0; j < 4; j++)
                    wmma::mma_sync(acc[i][j], af[i], bf[j], acc[i][j]);
        }
        __syncthreads();
    }

    // ---- epilogue: stage 16x16 frags through smem (reuse As), add bias,
    //      drain with float4 stores (STG.128) ----
    float* stg = &As[wid * 256 * 2];   // 2KB region per warp inside As (8*512 floats <= 20480)
#pragma unroll
    for (int i = 0; i < 2; i++) {
#pragma unroll
        for (int j = 0; j < 4; j++) {
            wmma::store_matrix_sync(stg, acc[i][j], 16, wmma::mem_row_major);
            __syncwarp();
            int r0 = row0 + wrow * 32 + i * 16;
            int c0 = col0 + wcol * 64 + j * 16;
            int rr  = lane >> 2;          // 0..7
            int cc4 = (lane & 3) * 4;     // 0,4,8,12
            float4 bv = *reinterpret_cast<const float4*>(&bias[c0 + cc4]);
#pragma unroll
            for (int h = 0; h < 2; h++) {
                int r  = rr + h * 8;
                int gr = r0 + r;
                if (gr < M) {
                    float4 v = *reinterpret_cast<float4*>(&stg[r * 16 + cc4]);
                    v.x += bv.x; v.y += bv.y; v.z += bv.z; v.w += bv.w;
                    *reinterpret_cast<float4*>(&out[(size_t)gr * D_N + c0 + cc4]) = v;
                }
            }
            __syncwarp();
        }
    }
}

// ---------------------------------------------------------------------------
// Launch
// ---------------------------------------------------------------------------
extern "C" void kernel_launch(void* const* d_in, const int* in_sizes, int n_in,
                              void* d_out, int out_size) {
    const float* x    = (const float*)d_in[0];
    const int*   ei   = (const int*)d_in[1];   // (2, E) row-major: first E = sources
    const float* W    = (const float*)d_in[2];
    const float* bias = (const float*)d_in[3];
    float*       out  = (float*)d_out;

    const int M = in_sizes[0] / D_K;       // 100000
    const int E = in_sizes[1] / 2;         // 3200000

    zero_deg_kernel<<<(M + 255) / 256, 256>>>(M);

    int n4 = E >> 2;
    int hblocks = (n4 + 255) / 256;
    if (hblocks > 2048) hblocks = 2048;
    if (hblocks < 1) hblocks = 1;
    hist_kernel<<<hblocks, 256>>>(ei, E);

    // Column block fastest-varying -> adjacent CTAs share the same x rows (L2 reuse)
    dim3 grid(D_N / BN, (M + BM - 1) / BM);   // (2, 782)
    gemm_scaled_kernel<<<grid, 256>>>(x, W, bias, out, M);
}

// round 5
// speedup vs baseline: 1.0647x; 1.0647x over previous
#include <cuda_runtime.h>
#include <cuda_bf16.h>
#include <mma.h>
#include <cstdint>

using namespace nvcuda;

#define N_NODES_MAX 100000
#define D_K 256     // D_IN
#define D_N 256     // D_OUT

// Scratch: per-node degree counters (allocation-free rule -> __device__ global)
__device__ int g_deg[N_NODES_MAX];

// ---------------------------------------------------------------------------
// Kernel 1: zero the degree counters (graph replays require re-zeroing)
// ---------------------------------------------------------------------------
__global__ void zero_deg_kernel(int n) {
    int i = blockIdx.x * blockDim.x + threadIdx.x;
    if (i < n) g_deg[i] = 0;
}

// ---------------------------------------------------------------------------
// Kernel 2: degree histogram over edge sources (edge_index[0, :])
// ---------------------------------------------------------------------------
__global__ void hist_kernel(const int* __restrict__ src, int n_edges) {
    int i = blockIdx.x * blockDim.x + threadIdx.x;
    int stride = gridDim.x * blockDim.x;
    int n4 = n_edges >> 2;
    const int4* src4 = reinterpret_cast<const int4*>(src);
    for (int j = i; j < n4; j += stride) {
        int4 v = __ldg(&src4[j]);
        atomicAdd(&g_deg[v.x], 1);
        atomicAdd(&g_deg[v.y], 1);
        atomicAdd(&g_deg[v.z], 1);
        atomicAdd(&g_deg[v.w], 1);
    }
    for (int j = (n4 << 2) + i; j < n_edges; j += stride) {
        atomicAdd(&g_deg[__ldg(&src[j])], 1);
    }
}

// ---------------------------------------------------------------------------
// cp.async helpers
// ---------------------------------------------------------------------------
__device__ __forceinline__ uint32_t smem_u32(const void* p) {
    return (uint32_t)__cvta_generic_to_shared(p);
}
// Predicated 16B async copy: src-size 0 -> zero-fill. Caller must pass a
// VALID (clamped) address even when !valid.
__device__ __forceinline__ void cp_async16(uint32_t dst, const void* src, bool valid) {
    int sz = valid ? 16 : 0;
    asm volatile("cp.async.cg.shared.global [%0], [%1], 16, %2;\n"
                 :: "r"(dst), "l"(src), "r"(sz));
}
__device__ __forceinline__ void cp_commit() {
    asm volatile("cp.async.commit_group;\n" ::: "memory");
}
template <int N>
__device__ __forceinline__ void cp_wait() {
    asm volatile("cp.async.wait_group %0;\n" :: "n"(N) : "memory");
}

// ---------------------------------------------------------------------------
// Kernel 3: out = diag(1 + deg) * (x @ W^T) + b
// tf32 tensor-core GEMM, cp.async double-buffered mainloop.
// deg applied in the EPILOGUE (algebraically identical, fp32-exact).
//
// Block tile: 128 x 128, BK = 16, 2-stage pipeline (40 KB static smem,
// 2 CTAs/SM). 8 warps: wrow = wid & 3 (32-row slice), wcol = wid >> 2
// (64-col slice), 2x4 accumulator fragments of 16x16, k-step 8.
// ---------------------------------------------------------------------------
#define BM 128
#define BN 128
#define BK 16
#define TS 20              // smem row stride in floats (80 B, conflict-padded)
#define NCHUNK (D_K / BK)  // 16

__global__ __launch_bounds__(256, 2)
void gemm_scaled_kernel(const float* __restrict__ x,
                        const float* __restrict__ W,
                        const float* __restrict__ bias,
                        float* __restrict__ out,
                        int M) {
    __shared__ __align__(16) float As[2][BM * TS];   // 2 x 10240 B
    __shared__ __align__(16) float Bs[2][BN * TS];   // 2 x 10240 B

    const int tid  = threadIdx.x;
    const int wid  = tid >> 5;
    const int lane = tid & 31;
    const int wrow = wid & 3;   // 0..3 -> 32-row slice
    const int wcol = wid >> 2;  // 0..1 -> 64-col slice

    const int row0 = blockIdx.y * BM;
    const int col0 = blockIdx.x * BN;

    // Per-thread load coords: 512 float4 per tile, 2 per thread.
    const int r_ld  = tid >> 2;          // 0..63 ; second row = r_ld + 64
    const int c4_ld = tid & 3;           // float4 col 0..3

    // Precompute clamped A row pointers + validity (stable across k-chunks).
    const float* a_src[2];
    bool a_ok[2];
#pragma unroll
    for (int it = 0; it < 2; it++) {
        int gr = row0 + r_ld + it * 64;
        a_ok[it]  = (gr < M);
        a_src[it] = &x[(size_t)(a_ok[it] ? gr : 0) * D_K + c4_ld * 4];
    }
    const float* b_src[2];
#pragma unroll
    for (int it = 0; it < 2; it++)
        b_src[it] = &W[(size_t)(col0 + r_ld + it * 64) * D_K + c4_ld * 4];

    wmma::fragment<wmma::accumulator, 16, 16, 8, float> acc[2][4];
#pragma unroll
    for (int i = 0; i < 2; i++)
#pragma unroll
        for (int j = 0; j < 4; j++)
            wmma::fill_fragment(acc[i][j], 0.0f);

    // ---- async tile loader for chunk c into buffer b ----
    auto load_tiles = [&](int c, int b) {
        int k0 = c * BK;
#pragma unroll
        for (int it = 0; it < 2; it++) {
            int r = r_ld + it * 64;
            cp_async16(smem_u32(&As[b][r * TS + c4_ld * 4]), a_src[it] + k0, a_ok[it]);
        }
#pragma unroll
        for (int it = 0; it < 2; it++) {
            int n = r_ld + it * 64;
            cp_async16(smem_u32(&Bs[b][n * TS + c4_ld * 4]), b_src[it] + k0, true);
        }
        cp_commit();
    };

    // ---- pipeline ----
    load_tiles(0, 0);
    int cur = 0;
#pragma unroll 1
    for (int c = 0; c < NCHUNK; c++) {
        if (c + 1 < NCHUNK) {
            load_tiles(c + 1, cur ^ 1);
            cp_wait<1>();
        } else {
            cp_wait<0>();
        }
        __syncthreads();

#pragma unroll
        for (int kk = 0; kk < BK; kk += 8) {
            wmma::fragment<wmma::matrix_a, 16, 16, 8, wmma::precision::tf32, wmma::row_major> af[2];
            wmma::fragment<wmma::matrix_b, 16, 16, 8, wmma::precision::tf32, wmma::col_major> bf[4];
#pragma unroll
            for (int i = 0; i < 2; i++) {
                wmma::load_matrix_sync(af[i], &As[cur][(wrow * 32 + i * 16) * TS + kk], TS);
#pragma unroll
                for (int t = 0; t < af[i].num_elements; t++)
                    af[i].x[t] = wmma::__float_to_tf32(af[i].x[t]);
            }
#pragma unroll
            for (int j = 0; j < 4; j++) {
                wmma::load_matrix_sync(bf[j], &Bs[cur][(wcol * 64 + j * 16) * TS + kk], TS);
#pragma unroll
                for (int t = 0; t < bf[j].num_elements; t++)
                    bf[j].x[t] = wmma::__float_to_tf32(bf[j].x[t]);
            }
#pragma unroll
            for (int i = 0; i < 2; i++)
#pragma unroll
                for (int j = 0; j < 4; j++)
                    wmma::mma_sync(acc[i][j], af[i], bf[j], acc[i][j]);
        }
        __syncthreads();
        cur ^= 1;
    }

    // ---- epilogue: scale by (1+deg), add bias, STG.128 ----
    const int rr  = lane >> 2;          // 0..7
    const int cc4 = (lane & 3) * 4;     // 0,4,8,12
    float dreg[2][2];
#pragma unroll
    for (int i = 0; i < 2; i++)
#pragma unroll
        for (int h = 0; h < 2; h++) {
            int gr = row0 + wrow * 32 + i * 16 + rr + h * 8;
            dreg[i][h] = (gr < M) ? (1.0f + (float)g_deg[gr]) : 0.0f;
        }

    float* stg = &As[0][0] + wid * 512;   // 512 floats per warp (8*512 fits As)
#pragma unroll
    for (int i = 0; i < 2; i++) {
#pragma unroll
        for (int j = 0; j < 4; j++) {
            wmma::store_matrix_sync(stg, acc[i][j], 16, wmma::mem_row_major);
            __syncwarp();
            int r0 = row0 + wrow * 32 + i * 16;
            int c0 = col0 + wcol * 64 + j * 16;
            float4 bv = *reinterpret_cast<const float4*>(&bias[c0 + cc4]);
#pragma unroll
            for (int h = 0; h < 2; h++) {
                int r  = rr + h * 8;
                int gr = r0 + r;
                if (gr < M) {
                    float d = dreg[i][h];
                    float4 v = *reinterpret_cast<float4*>(&stg[r * 16 + cc4]);
                    v.x = fmaf(d, v.x, bv.x);
                    v.y = fmaf(d, v.y, bv.y);
                    v.z = fmaf(d, v.z, bv.z);
                    v.w = fmaf(d, v.w, bv.w);
                    *reinterpret_cast<float4*>(&out[(size_t)gr * D_N + c0 + cc4]) = v;
                }
            }
            __syncwarp();
        }
    }
}

// ---------------------------------------------------------------------------
// Launch
// ---------------------------------------------------------------------------
extern "C" void kernel_launch(void* const* d_in, const int* in_sizes, int n_in,
                              void* d_out, int out_size) {
    const float* x    = (const float*)d_in[0];
    const int*   ei   = (const int*)d_in[1];   // (2, E) row-major: first E = sources
    const float* W    = (const float*)d_in[2];
    const float* bias = (const float*)d_in[3];
    float*       out  = (float*)d_out;

    const int M = in_sizes[0] / D_K;       // 100000
    const int E = in_sizes[1] / 2;         // 3200000

    zero_deg_kernel<<<(M + 255) / 256, 256>>>(M);

    int n4 = E >> 2;
    int hblocks = (n4 + 255) / 256;
    if (hblocks > 2048) hblocks = 2048;
    if (hblocks < 1) hblocks = 1;
    hist_kernel<<<hblocks, 256>>>(ei, E);

    // Column block fastest-varying -> adjacent CTAs share the same x rows (L2 reuse)
    dim3 grid(D_N / BN, (M + BM - 1) / BM);   // (2, 782)
    gemm_scaled_kernel<<<grid, 256>>>(x, W, bias, out, M);
}